// round 8
// baseline (speedup 1.0000x reference)
#include <cuda_runtime.h>

#define Hdim  100
#define T_IN  1000
#define T_TOT 1300
#define NB    4
#define NCTA  128
#define NTHR  832   // 26 warps: A = warps 0-12 (tid<416), B = warps 13-25

// Gate-quad weights: [k*100 + j] -> float4 (i, f, g, o)
__device__ float4 g_W1Q [Hdim*Hdim];   // W_hh1
__device__ float4 g_W2IQ[Hdim*Hdim];   // W_ih2
__device__ float4 g_W2HQ[Hdim*Hdim];   // W_hh2
__device__ float4 g_WI1Q[Hdim];        // W_ih1 gate-quad per unit
__device__ float4 g_B1Q [Hdim];        // b_ih1+b_hh1 gate-quad
__device__ float4 g_B2Q [Hdim];

__global__ void prep_weights(const float* __restrict__ W_hh1,
                             const float* __restrict__ W_ih2,
                             const float* __restrict__ W_hh2,
                             const float* __restrict__ W_ih1,
                             const float* __restrict__ b_ih1,
                             const float* __restrict__ b_hh1,
                             const float* __restrict__ b_ih2,
                             const float* __restrict__ b_hh2) {
    int i = blockIdx.x * blockDim.x + threadIdx.x;
    if (i < Hdim * Hdim) {
        int k = i / Hdim, j = i % Hdim;
        g_W1Q[i]  = make_float4(W_hh1[j*Hdim+k],          W_hh1[(Hdim+j)*Hdim+k],
                                W_hh1[(2*Hdim+j)*Hdim+k], W_hh1[(3*Hdim+j)*Hdim+k]);
        g_W2IQ[i] = make_float4(W_ih2[j*Hdim+k],          W_ih2[(Hdim+j)*Hdim+k],
                                W_ih2[(2*Hdim+j)*Hdim+k], W_ih2[(3*Hdim+j)*Hdim+k]);
        g_W2HQ[i] = make_float4(W_hh2[j*Hdim+k],          W_hh2[(Hdim+j)*Hdim+k],
                                W_hh2[(2*Hdim+j)*Hdim+k], W_hh2[(3*Hdim+j)*Hdim+k]);
    }
    if (i < Hdim) {
        g_WI1Q[i] = make_float4(W_ih1[i], W_ih1[Hdim+i], W_ih1[2*Hdim+i], W_ih1[3*Hdim+i]);
        g_B1Q[i]  = make_float4(b_ih1[i]        + b_hh1[i],
                                b_ih1[Hdim+i]   + b_hh1[Hdim+i],
                                b_ih1[2*Hdim+i] + b_hh1[2*Hdim+i],
                                b_ih1[3*Hdim+i] + b_hh1[3*Hdim+i]);
        g_B2Q[i]  = make_float4(b_ih2[i]        + b_hh2[i],
                                b_ih2[Hdim+i]   + b_hh2[Hdim+i],
                                b_ih2[2*Hdim+i] + b_hh2[2*Hdim+i],
                                b_ih2[3*Hdim+i] + b_hh2[3*Hdim+i]);
    }
}

typedef unsigned long long u64;
typedef ulonglong2 u64x2;

__device__ __forceinline__ u64 pack2(float v) {
    u64 r; asm("mov.b64 %0, {%1, %1};" : "=l"(r) : "f"(v)); return r;
}
__device__ __forceinline__ u64 packpair(float a, float b) {
    u64 r; asm("mov.b64 %0, {%1, %2};" : "=l"(r) : "f"(a), "f"(b)); return r;
}
__device__ __forceinline__ void unpack2(u64 v, float& a, float& b) {
    asm("mov.b64 {%0, %1}, %2;" : "=f"(a), "=f"(b) : "l"(v));
}
__device__ __forceinline__ void fma2(u64& a, u64 w, u64 h) {
    asm("fma.rn.f32x2 %0, %1, %2, %0;" : "+l"(a) : "l"(w), "l"(h));
}
__device__ __forceinline__ float tanhfast(float x) {
    float y; asm("tanh.approx.f32 %0, %1;" : "=f"(y) : "f"(x)); return y;
}
__device__ __forceinline__ float sigfast(float x) {
    return fmaf(0.5f, tanhfast(0.5f * x), 0.5f);
}

// Layer-1 gate+cell for thread (j, b): 4 gates over 100 k, W1 in smem.
__device__ __forceinline__ void l1_step(const u64x2* __restrict__ W1s,
                                        const float* __restrict__ hR,
                                        float* __restrict__ hW,
                                        float x,
                                        u64 b1if, u64 b1go, u64 wiif, u64 wigo,
                                        float& c1, int j, int b) {
    u64 aif = b1if, ago = b1go;
    const u64 xp = pack2(x);
    fma2(aif, wiif, xp); fma2(ago, wigo, xp);
    const u64x2* wp = W1s + j;
    #pragma unroll 10
    for (int k = 0; k < Hdim; ++k) {
        const u64x2 wv = wp[k * Hdim];          // LDS.128, 8-way dedup -> 1 wf
        const u64   hp = pack2(hR[k*4 + b]);    // LDS.32 broadcast -> 1 wf
        fma2(aif, wv.x, hp);
        fma2(ago, wv.y, hp);
    }
    float vi, vf, vg, vo;
    unpack2(aif, vi, vf); unpack2(ago, vg, vo);
    c1 = fmaf(sigfast(vf), c1, sigfast(vi) * tanhfast(vg));
    hW[j*4 + b] = sigfast(vo) * tanhfast(c1);
}

// Layer-2 gate+cell for thread (j, b): 4 gates over 200 k (h1 | h2), W2 from L2.
__device__ __forceinline__ void l2_step(const float* __restrict__ h1,
                                        const float* __restrict__ h2R,
                                        float* __restrict__ h2W,
                                        u64 b2if, u64 b2go,
                                        float& c2, int j, int b) {
    u64 aif = b2if, ago = b2go;
    const u64x2* wi = (const u64x2*)g_W2IQ + j;
    #pragma unroll 5
    for (int k = 0; k < Hdim; ++k) {
        const u64x2 wv = __ldg(wi + k * Hdim);  // LDG.128, 8-way dedup
        const u64   hp = pack2(h1[k*4 + b]);
        fma2(aif, wv.x, hp);
        fma2(ago, wv.y, hp);
    }
    const u64x2* wh = (const u64x2*)g_W2HQ + j;
    #pragma unroll 5
    for (int k = 0; k < Hdim; ++k) {
        const u64x2 wv = __ldg(wh + k * Hdim);
        const u64   hp = pack2(h2R[k*4 + b]);
        fma2(aif, wv.x, hp);
        fma2(ago, wv.y, hp);
    }
    float vi, vf, vg, vo;
    unpack2(aif, vi, vf); unpack2(ago, vg, vo);
    c2 = fmaf(sigfast(vf), c2, sigfast(vi) * tanhfast(vg));
    h2W[j*4 + b] = sigfast(vo) * tanhfast(c2);
}

// y projection: warps 0-3 (one per batch), reads h2R.
__device__ __forceinline__ void proj_y(const float* __restrict__ h2R,
                                       const float* __restrict__ wlin, float blin,
                                       float* __restrict__ ysv,
                                       float* __restrict__ out,
                                       int b0, int t, int tid) {
    const int w = tid >> 5, l = tid & 31;
    float s = 0.f;
    #pragma unroll
    for (int j0 = 0; j0 < Hdim; j0 += 32) {
        const int j = j0 + l;
        if (j < Hdim) s = fmaf(h2R[j*4 + w], wlin[j], s);
    }
    #pragma unroll
    for (int o = 16; o > 0; o >>= 1) s += __shfl_down_sync(0xffffffffu, s, o);
    if (l == 0) {
        const float y = s + blin;
        out[(b0 + w) * T_TOT + t] = y;
        ysv[w] = y;
    }
}

__global__ __launch_bounds__(NTHR, 1)
void lstm2_kernel(const float* __restrict__ input,
                  const float* __restrict__ W_lin,
                  const float* __restrict__ b_lin,
                  float* __restrict__ out)
{
    extern __shared__ float sm[];
    u64x2* W1s  = (u64x2*)sm;            // [10000] gate-quads (160000 B)
    float* h1b  = sm + 40000;            // [2][400] ping-pong  (40000..40800)
    float* h2b  = sm + 40800;            // [2][400]            (40800..41600)
    float* xin  = sm + 41600;            // [1000][4] t-major input
    float* ysv  = sm + 45600;            // [4]
    float* wlin = sm + 45604;            // [100]
    // total 45704 floats = 182816 B

    const int tid  = threadIdx.x;
    const int b0   = blockIdx.x * NB;
    const bool grpA = (tid < 416);
    const int  bt   = tid - 416;
    const bool actA = grpA && tid < 400;
    const bool actB = !grpA && bt < 400;
    const int  j    = (grpA ? tid : bt) >> 2;
    const int  b    = (grpA ? tid : bt) & 3;

    // ---- one-time init (h1b+h2b are contiguous: exactly 1600 floats) ----
    for (int i = tid; i < Hdim * Hdim * 4; i += NTHR)
        ((float*)W1s)[i] = ((const float*)g_W1Q)[i];
    for (int i = tid; i < 1600; i += NTHR) sm[40000 + i] = 0.f;
    for (int i = tid; i < NB * T_IN; i += NTHR) {
        int t = i >> 2, bb = i & 3;
        xin[i] = input[(b0 + bb) * T_IN + t];
    }
    if (tid < Hdim) wlin[tid] = W_lin[tid];
    if (tid < NB)   ysv[tid]  = 0.f;
    const float blin_r = __ldg(b_lin);

    u64 b1if = 0, b1go = 0, wiif = 0, wigo = 0, b2if = 0, b2go = 0;
    if (actA) {
        const float4 bq = g_B1Q[j], wq = g_WI1Q[j];
        b1if = packpair(bq.x, bq.y); b1go = packpair(bq.z, bq.w);
        wiif = packpair(wq.x, wq.y); wigo = packpair(wq.z, wq.w);
    } else if (actB) {
        const float4 bq = g_B2Q[j];
        b2if = packpair(bq.x, bq.y); b2go = packpair(bq.z, bq.w);
    }
    float c1 = 0.f, c2 = 0.f;

    float* h1R = h1b;       float* h1W = h1b + 400;
    float* h2R = h2b;       float* h2W = h2b + 400;
    __syncthreads();

    // ======== teacher-forced pipeline: tick t: A does L1(t), B does L2(t-1),
    //          warps 0-3 project y(t-2). One barrier per tick. ========
    for (int tick = 0; tick <= T_IN; ++tick) {
        if (grpA) {
            if (actA && tick < T_IN)
                l1_step(W1s, h1R, h1W, xin[tick*4 + b],
                        b1if, b1go, wiif, wigo, c1, j, b);
            if (tid < 128 && tick >= 2)
                proj_y(h2R, wlin, blin_r, ysv, out, b0, tick - 2, tid);
        } else if (actB && tick >= 1) {
            l2_step(h1R, h2R, h2W, b2if, b2go, c2, j, b);
        }
        __syncthreads();
        if (tick < T_IN) { float* t_ = h1R; h1R = h1W; h1W = t_; }
        if (tick >= 1)   { float* t_ = h2R; h2R = h2W; h2W = t_; }
    }
    // state now: h1R=h1(999), h2R=h2(999); y(0..998) written.

    // ======== autoregressive serial phase: t = 1000..1299 ========
    for (int t = T_IN; t < T_TOT; ++t) {
        if (tid < 128)
            proj_y(h2R, wlin, blin_r, ysv, out, b0, t - 1, tid);   // y(t-1)
        __syncthreads();
        if (actA)
            l1_step(W1s, h1R, h1W, ysv[b], b1if, b1go, wiif, wigo, c1, j, b);
        __syncthreads();
        if (actB)
            l2_step(h1W, h2R, h2W, b2if, b2go, c2, j, b);          // uses new h1
        __syncthreads();
        { float* t_ = h1R; h1R = h1W; h1W = t_; }
        { float* t_ = h2R; h2R = h2W; h2W = t_; }
    }
    if (tid < 128)
        proj_y(h2R, wlin, blin_r, ysv, out, b0, T_TOT - 1, tid);   // y(1299)
}

extern "C" void kernel_launch(void* const* d_in, const int* in_sizes, int n_in,
                              void* d_out, int out_size) {
    const float* input = (const float*)d_in[0];
    const float* W_ih1 = (const float*)d_in[1];
    const float* W_hh1 = (const float*)d_in[2];
    const float* b_ih1 = (const float*)d_in[3];
    const float* b_hh1 = (const float*)d_in[4];
    const float* W_ih2 = (const float*)d_in[5];
    const float* W_hh2 = (const float*)d_in[6];
    const float* b_ih2 = (const float*)d_in[7];
    const float* b_hh2 = (const float*)d_in[8];
    const float* W_lin = (const float*)d_in[9];
    const float* b_lin = (const float*)d_in[10];
    float* out = (float*)d_out;

    prep_weights<<<(Hdim*Hdim + 255) / 256, 256>>>(W_hh1, W_ih2, W_hh2,
                                                   W_ih1, b_ih1, b_hh1,
                                                   b_ih2, b_hh2);

    const int smem_bytes = 45704 * (int)sizeof(float);
    cudaFuncSetAttribute(lstm2_kernel,
                         cudaFuncAttributeMaxDynamicSharedMemorySize, smem_bytes);
    lstm2_kernel<<<NCTA, NTHR, smem_bytes>>>(input, W_lin, b_lin, out);
}

// round 9
// speedup vs baseline: 1.5054x; 1.5054x over previous
#include <cuda_runtime.h>

#define Hdim  100
#define Gdim  400
#define T_IN  1000
#define T_TOT 1300
#define NB    4
#define NCTA  128
#define NTHR  800

// Pre-packed transposed weights (same layouts as the 8561us kernel).
__device__ float2 g_W1P[50 * Gdim];    // W_hh1^T  [k2][g]  (k-pairs)
__device__ float4 g_W2Q[50 * Gdim];    // [W_ih2;W_hh2]^T [k4][g]  (k-quads)

__global__ void prep_weights(const float* __restrict__ W_hh1,
                             const float* __restrict__ W_ih2,
                             const float* __restrict__ W_hh2) {
    int i = blockIdx.x * blockDim.x + threadIdx.x;
    if (i >= 50 * Gdim) return;
    int kq = i / Gdim, g = i % Gdim;
    g_W1P[i] = make_float2(W_hh1[g*Hdim + 2*kq], W_hh1[g*Hdim + 2*kq + 1]);
    float4 v;
    {
        int k = 4 * kq;
        const float* src = (k < Hdim) ? (W_ih2 + g*Hdim + k) : (W_hh2 + g*Hdim + k - Hdim);
        v.x = src[0]; v.y = src[1]; v.z = src[2]; v.w = src[3];
    }
    g_W2Q[i] = v;
}

typedef unsigned long long u64;
typedef ulonglong2 u64x2;

__device__ __forceinline__ u64 pack2(float v) {
    u64 r; asm("mov.b64 %0, {%1, %1};" : "=l"(r) : "f"(v)); return r;
}
__device__ __forceinline__ void fma2(u64& a, u64 w, u64 h) {
    asm("fma.rn.f32x2 %0, %1, %2, %0;" : "+l"(a) : "l"(w), "l"(h));
}
__device__ __forceinline__ float tanhfast(float x) {
    float y; asm("tanh.approx.f32 %0, %1;" : "=f"(y) : "f"(x)); return y;
}
__device__ __forceinline__ float sigfast(float x) {
    return fmaf(0.5f, tanhfast(0.5f * x), 0.5f);
}

// L1 gate partial: 25 k-pairs from k2_0, W1 in smem, h from h1 (float4 per k).
__device__ __forceinline__ u64x2 l1_gates(const float2* __restrict__ W1s, int g,
                                          int k2_0, const float4* __restrict__ h1,
                                          u64x2 xp, bool applyx, u64 bb1, u64 wi) {
    u64 a0, a1;
    if (applyx) { a0 = bb1; a1 = bb1; fma2(a0, wi, xp.x); fma2(a1, wi, xp.y); }
    else        { a0 = 0ull; a1 = 0ull; }
    const float2* wp = W1s + g;
    #pragma unroll 5
    for (int k2 = k2_0; k2 < k2_0 + 25; ++k2) {
        const float2 w = wp[k2 * Gdim];
        const u64 w0 = pack2(w.x), w1 = pack2(w.y);
        const u64x2 h0 = *(const u64x2*)(h1 + 2*k2);
        const u64x2 h1v = *(const u64x2*)(h1 + 2*k2 + 1);
        fma2(a0, w0, h0.x); fma2(a1, w0, h0.y);
        fma2(a0, w1, h1v.x); fma2(a1, w1, h1v.y);
    }
    u64x2 r; r.x = a0; r.y = a1; return r;
}

// L2 gate partial: 25 k-quads (W row kw0+q), h from hb (local quads q).
__device__ __forceinline__ u64x2 l2_gates(int g, int kw0,
                                          const float4* __restrict__ hb,
                                          u64 bb2, bool applyb) {
    u64 a0 = applyb ? bb2 : 0ull, a1 = a0;
    const float4* wp = g_W2Q + g;
    #pragma unroll 5
    for (int q = 0; q < 25; ++q) {
        const float4 w = __ldg(wp + (kw0 + q) * Gdim);
        const u64 w0 = pack2(w.x), w1 = pack2(w.y);
        const u64 w2 = pack2(w.z), w3 = pack2(w.w);
        const u64x2 h0 = *(const u64x2*)(hb + 4*q);
        const u64x2 h1 = *(const u64x2*)(hb + 4*q + 1);
        const u64x2 h2 = *(const u64x2*)(hb + 4*q + 2);
        const u64x2 h3 = *(const u64x2*)(hb + 4*q + 3);
        fma2(a0, w0, h0.x); fma2(a1, w0, h0.y);
        fma2(a0, w1, h1.x); fma2(a1, w1, h1.y);
        fma2(a0, w2, h2.x); fma2(a1, w2, h2.y);
        fma2(a0, w3, h3.x); fma2(a1, w3, h3.y);
    }
    u64x2 r; r.x = a0; r.y = a1; return r;
}

__device__ __forceinline__ void cell_up(const float* __restrict__ gA,
                                        const float* __restrict__ gB,
                                        float* __restrict__ hW,
                                        float& c, int cj, int cb) {
    const float vi = gA[(cj         )*4 + cb] + gB[(cj         )*4 + cb];
    const float vf = gA[(cj +   Hdim)*4 + cb] + gB[(cj +   Hdim)*4 + cb];
    const float vg = gA[(cj + 2*Hdim)*4 + cb] + gB[(cj + 2*Hdim)*4 + cb];
    const float vo = gA[(cj + 3*Hdim)*4 + cb] + gB[(cj + 3*Hdim)*4 + cb];
    c = fmaf(sigfast(vf), c, sigfast(vi) * tanhfast(vg));
    hW[cj*4 + cb] = sigfast(vo) * tanhfast(c);
}

__device__ __forceinline__ void proj_y(const float* __restrict__ h2,
                                       const float* __restrict__ wlin, float blin,
                                       float* __restrict__ ysv,
                                       float* __restrict__ out,
                                       int b0, int t, int tid) {
    const int w = tid >> 5, l = tid & 31;
    float s = 0.f;
    #pragma unroll
    for (int j0 = 0; j0 < Hdim; j0 += 32) {
        const int j = j0 + l;
        if (j < Hdim) s = fmaf(h2[j*4 + w], wlin[j], s);
    }
    #pragma unroll
    for (int o = 16; o > 0; o >>= 1) s += __shfl_down_sync(0xffffffffu, s, o);
    if (l == 0) {
        const float y = s + blin;
        out[(b0 + w) * T_TOT + t] = y;
        ysv[w] = y;
    }
}

__global__ __launch_bounds__(NTHR, 1)
void lstm2_kernel(const float* __restrict__ input,
                  const float* __restrict__ W_ih1,
                  const float* __restrict__ b_ih1,
                  const float* __restrict__ b_hh1,
                  const float* __restrict__ b_ih2,
                  const float* __restrict__ b_hh2,
                  const float* __restrict__ W_lin,
                  const float* __restrict__ b_lin,
                  float* __restrict__ out)
{
    extern __shared__ float sm[];
    float2* W1s  = (float2*)sm;                 //     0..40000  W_hh1^T
    float4* h1a  = (float4*)(sm + 40000);       // 40000..40400
    float4* h1b  = (float4*)(sm + 40400);       // 40400..40800
    float4* h2a  = (float4*)(sm + 40800);       // 40800..41200
    float4* h2b  = (float4*)(sm + 41200);       // 41200..41600
    u64x2*  g1A  = (u64x2*)(sm + 41600);        // 41600..43200
    u64x2*  g1B  = (u64x2*)(sm + 43200);        // 43200..44800
    u64x2*  g2A  = (u64x2*)(sm + 44800);        // 44800..46400
    u64x2*  g2B  = (u64x2*)(sm + 46400);        // 46400..48000
    float4* xin4 = (float4*)(sm + 48000);       // 48000..52000  input t-major
    float*  ysv  = sm + 52000;                  // [4]
    float*  wlin = sm + 52004;                  // [100]
    // total 52104 floats = 208416 B

    const int tid  = threadIdx.x;
    const int b0   = blockIdx.x * NB;
    const bool hA  = (tid < Gdim);
    const int  g   = hA ? tid : tid - Gdim;
    const int  k2L1 = hA ? 0 : 25;   // L1 k-pair start
    const int  kw0  = hA ? 0 : 25;   // L2 k-quad start (A: h1 part, B: h2 part)

    // ---- one-time init ----
    for (int i = tid; i < 50 * Gdim; i += NTHR) W1s[i] = g_W1P[i];
    for (int i = tid; i < 1600; i += NTHR) sm[40000 + i] = 0.f;   // h1a..h2b
    for (int i = tid; i < NB * T_IN; i += NTHR) {
        int t = i >> 2, bb = i & 3;
        ((float*)xin4)[i] = input[(b0 + bb) * T_IN + t];
    }
    if (tid < Hdim) wlin[tid] = W_lin[tid];
    const float blin_r = __ldg(b_lin);

    const u64 bb1p = hA ? pack2(b_ih1[g] + b_hh1[g]) : 0ull;
    const u64 bb2p = hA ? pack2(b_ih2[g] + b_hh2[g]) : 0ull;
    const u64 wip  = hA ? pack2(W_ih1[g]) : 0ull;

    const int cj = tid >> 2, cb = tid & 3;    // cell role (tid<400)
    float c1 = 0.f, c2 = 0.f;

    float4 *h1cur = h1a, *h1nxt = h1b, *h2prv = h2a, *h2cur = h2b;
    __syncthreads();

    // ---- prologue: L1 gates(0) + cell ----
    {
        const u64x2 xp = *(const u64x2*)(xin4 + 0);
        const u64x2 r1 = l1_gates(W1s, g, k2L1, h1cur, xp, hA, bb1p, wip);
        if (hA) g1A[g] = r1; else g1B[g] = r1;
        __syncthreads();
        if (tid < Gdim) cell_up((const float*)g1A, (const float*)g1B,
                                (float*)h1nxt, c1, cj, cb);
        __syncthreads();
        float4* t_ = h1cur; h1cur = h1nxt; h1nxt = t_;     // h1cur = h1(0)
    }

    // ---- teacher-forced fused loop: t = 0..998, 2 barriers per step ----
    for (int t = 0; t < T_IN - 1; ++t) {
        // G phase: L2 gates(t)  +  L1 gates(t+1)  +  proj y(t-1)
        const u64x2 r2 = l2_gates(g, kw0, hA ? h1cur : h2prv, bb2p, hA);
        const u64x2 xp = *(const u64x2*)(xin4 + (t + 1));
        const u64x2 r1 = l1_gates(W1s, g, k2L1, h1cur, xp, hA, bb1p, wip);
        if (hA) { g2A[g] = r2; g1A[g] = r1; }
        else    { g2B[g] = r2; g1B[g] = r1; }
        if (tid < 128 && t >= 1)
            proj_y((const float*)h2prv, wlin, blin_r, ysv, out, b0, t - 1, tid);
        __syncthreads();
        // C phase: both cell updates
        if (tid < Gdim) {
            cell_up((const float*)g2A, (const float*)g2B, (float*)h2cur, c2, cj, cb);
            cell_up((const float*)g1A, (const float*)g1B, (float*)h1nxt, c1, cj, cb);
        }
        __syncthreads();
        float4* t1 = h1cur; h1cur = h1nxt; h1nxt = t1;
        float4* t2 = h2prv; h2prv = h2cur; h2cur = t2;
    }
    // state: h1cur=h1(999), h2prv=h2(998)

    // ---- drain: L2(999), y(998), y(999) ----
    {
        const u64x2 r2 = l2_gates(g, kw0, hA ? h1cur : h2prv, bb2p, hA);
        if (hA) g2A[g] = r2; else g2B[g] = r2;
        if (tid < 128)
            proj_y((const float*)h2prv, wlin, blin_r, ysv, out, b0, T_IN - 2, tid);
        __syncthreads();
        if (tid < Gdim) cell_up((const float*)g2A, (const float*)g2B,
                                (float*)h2cur, c2, cj, cb);
        __syncthreads();
        float4* t2 = h2prv; h2prv = h2cur; h2cur = t2;     // h2prv = h2(999)
        if (tid < 128)
            proj_y((const float*)h2prv, wlin, blin_r, ysv, out, b0, T_IN - 1, tid);
        __syncthreads();                                    // ysv = y(999)
    }

    // ---- autoregressive serial phase: t = 1000..1299 ----
    for (int t = T_IN; t < T_TOT; ++t) {
        const u64x2 xp = *(const u64x2*)ysv;
        const u64x2 r1 = l1_gates(W1s, g, k2L1, h1cur, xp, hA, bb1p, wip);
        if (hA) g1A[g] = r1; else g1B[g] = r1;
        __syncthreads();
        if (tid < Gdim) cell_up((const float*)g1A, (const float*)g1B,
                                (float*)h1nxt, c1, cj, cb);
        __syncthreads();
        { float4* t_ = h1cur; h1cur = h1nxt; h1nxt = t_; }  // h1cur = h1(t)
        const u64x2 r2 = l2_gates(g, kw0, hA ? h1cur : h2prv, bb2p, hA);
        if (hA) g2A[g] = r2; else g2B[g] = r2;
        __syncthreads();
        if (tid < Gdim) cell_up((const float*)g2A, (const float*)g2B,
                                (float*)h2cur, c2, cj, cb);
        __syncthreads();
        { float4* t_ = h2prv; h2prv = h2cur; h2cur = t_; }  // h2prv = h2(t)
        if (tid < 128)
            proj_y((const float*)h2prv, wlin, blin_r, ysv, out, b0, t, tid);
        __syncthreads();
    }
}

extern "C" void kernel_launch(void* const* d_in, const int* in_sizes, int n_in,
                              void* d_out, int out_size) {
    const float* input = (const float*)d_in[0];
    const float* W_ih1 = (const float*)d_in[1];
    const float* W_hh1 = (const float*)d_in[2];
    const float* b_ih1 = (const float*)d_in[3];
    const float* b_hh1 = (const float*)d_in[4];
    const float* W_ih2 = (const float*)d_in[5];
    const float* W_hh2 = (const float*)d_in[6];
    const float* b_ih2 = (const float*)d_in[7];
    const float* b_hh2 = (const float*)d_in[8];
    const float* W_lin = (const float*)d_in[9];
    const float* b_lin = (const float*)d_in[10];
    float* out = (float*)d_out;

    prep_weights<<<(50 * Gdim + 255) / 256, 256>>>(W_hh1, W_ih2, W_hh2);

    const int smem_bytes = 52104 * (int)sizeof(float);
    cudaFuncSetAttribute(lstm2_kernel,
                         cudaFuncAttributeMaxDynamicSharedMemorySize, smem_bytes);
    lstm2_kernel<<<NCTA, NTHR, smem_bytes>>>(input, W_ih1, b_ih1, b_hh1,
                                             b_ih2, b_hh2, W_lin, b_lin, out);
}

// round 10
// speedup vs baseline: 1.6870x; 1.1206x over previous
#include <cuda_runtime.h>
#include <cuda_fp16.h>

#define Hdim  100
#define Gdim  400
#define T_IN  1000
#define T_TOT 1300
#define NB    4
#define NCTA  128
#define NTHR  800

// Pre-packed transposed weights.
__device__ float2 g_W1P[50 * Gdim];   // W_hh1^T  [k2][g]  (fp32 k-pairs, smem-bound)
__device__ uint2  g_W2H[50 * Gdim];   // [W_ih2;W_hh2]^T [k4][g]  (fp16 k-quads)

__global__ void prep_weights(const float* __restrict__ W_hh1,
                             const float* __restrict__ W_ih2,
                             const float* __restrict__ W_hh2) {
    int i = blockIdx.x * blockDim.x + threadIdx.x;
    if (i >= 50 * Gdim) return;
    int kq = i / Gdim, g = i % Gdim;
    g_W1P[i] = make_float2(W_hh1[g*Hdim + 2*kq], W_hh1[g*Hdim + 2*kq + 1]);
    // W2 fp16 quad: k = 4kq .. 4kq+3  (k<100 -> W_ih2, else W_hh2)
    {
        int k = 4 * kq;
        const float* src = (k < Hdim) ? (W_ih2 + g*Hdim + k)
                                      : (W_hh2 + g*Hdim + k - Hdim);
        __half2 p0 = __floats2half2_rn(src[0], src[1]);
        __half2 p1 = __floats2half2_rn(src[2], src[3]);
        uint2 u;
        u.x = *reinterpret_cast<unsigned*>(&p0);
        u.y = *reinterpret_cast<unsigned*>(&p1);
        g_W2H[i] = u;
    }
}

typedef unsigned long long u64;
typedef ulonglong2 u64x2;

__device__ __forceinline__ u64 pack2(float v) {
    u64 r; asm("mov.b64 %0, {%1, %1};" : "=l"(r) : "f"(v)); return r;
}
__device__ __forceinline__ void fma2(u64& a, u64 w, u64 h) {
    asm("fma.rn.f32x2 %0, %1, %2, %0;" : "+l"(a) : "l"(w), "l"(h));
}
__device__ __forceinline__ float tanhfast(float x) {
    float y; asm("tanh.approx.f32 %0, %1;" : "=f"(y) : "f"(x)); return y;
}
__device__ __forceinline__ float sigfast(float x) {
    return fmaf(0.5f, tanhfast(0.5f * x), 0.5f);
}

__global__ __launch_bounds__(NTHR, 1)
void lstm2_kernel(const float* __restrict__ input,
                  const float* __restrict__ W_ih1,
                  const float* __restrict__ b_ih1,
                  const float* __restrict__ b_hh1,
                  const float* __restrict__ b_ih2,
                  const float* __restrict__ b_hh2,
                  const float* __restrict__ W_lin,
                  const float* __restrict__ b_lin,
                  float* __restrict__ out)
{
    extern __shared__ float sm[];
    float2*     W1s    = (float2*)sm;                    // [50*400] W_hh1^T packed
    float4*     hcat   = (float4*)(sm + 40000);          // [200] (h1|h2) x 4 batches
    ulonglong2* gatesA = (ulonglong2*)(hcat + 200);      // [400] partial (half A)
    ulonglong2* gatesB = gatesA + Gdim;                  // [400] partial (half B)
    float4*     xin    = (float4*)(gatesB + Gdim);       // [1000] input, t-major
    float4*     ysv    = xin + T_IN;                     // [1]  autoregressive x
    float*      wlin   = (float*)(ysv + 1);              // [100]
    // floats: 40000 + 800 + 1600 + 1600 + 4000 + 4 + 100 = 48104 (192416 B)

    const int tid  = threadIdx.x;
    const int b0   = blockIdx.x * NB;
    const bool hA  = (tid < Gdim);
    const int  g   = hA ? tid : tid - Gdim;

    // ---- one-time init ----
    for (int i = tid; i < 50 * Gdim; i += NTHR) W1s[i] = g_W1P[i];
    for (int i = tid; i < NB * T_IN; i += NTHR) {        // xin[t][b]
        int t = i >> 2, b = i & 3;
        ((float*)xin)[i] = input[(b0 + b) * T_IN + t];
    }
    if (tid < Hdim) wlin[tid] = W_lin[tid];
    for (int i = tid; i < 200 * 4; i += NTHR) ((float*)hcat)[i] = 0.f;
    const float blin_r = __ldg(b_lin);

    // per-thread constants (bias/x-weight only applied by half A)
    const u64 bb1p = hA ? pack2(b_ih1[g] + b_hh1[g]) : 0ull;
    const u64 bb2p = hA ? pack2(b_ih2[g] + b_hh2[g]) : 0ull;
    const u64 wip  = hA ? pack2(W_ih1[g]) : 0ull;
    const int k2L1 = hA ? 0 : 25;    // layer-1 k-pair start (k: 0..49 / 50..99)
    const int k4L2 = hA ? 0 : 25;    // layer-2 k-quad start (k: 0..99 / 100..199)

    const int cj = tid >> 2;         // cell role (tid < 400)
    const int cb = tid & 3;
    float c1 = 0.f, c2 = 0.f;
    __syncthreads();

    for (int t = 0; t < T_TOT; ++t) {
        // ---- Layer 1 gate partials (W1 fp32 from smem, conflict-free) ----
        {
            const u64x2 xp = (t < T_IN) ? *(const u64x2*)(xin + t)
                                        : *(const u64x2*)ysv;
            u64 a0 = bb1p, a1 = bb1p;
            if (hA) { fma2(a0, wip, xp.x); fma2(a1, wip, xp.y); }
            const float2* wp = W1s + g;
            #pragma unroll 5
            for (int k2 = k2L1; k2 < k2L1 + 25; ++k2) {
                const float2 w  = wp[k2 * Gdim];                       // coalesced
                const u64 w0 = pack2(w.x), w1 = pack2(w.y);
                const u64x2 h0 = *(const u64x2*)(hcat + 2*k2);         // broadcast
                const u64x2 h1 = *(const u64x2*)(hcat + 2*k2 + 1);
                fma2(a0, w0, h0.x); fma2(a1, w0, h0.y);
                fma2(a0, w1, h1.x); fma2(a1, w1, h1.y);
            }
            ulonglong2 r; r.x = a0; r.y = a1;
            if (hA) gatesA[g] = r; else gatesB[g] = r;
        }
        __syncthreads();                                  // #1 gates ready

        // ---- Layer 1 cell update (c1 in registers) ----
        if (tid < Gdim) {
            const float* gA = (const float*)gatesA;
            const float* gB = (const float*)gatesB;
            const float vi = gA[(cj         )*4 + cb] + gB[(cj         )*4 + cb];
            const float vf = gA[(cj +   Hdim)*4 + cb] + gB[(cj +   Hdim)*4 + cb];
            const float vg = gA[(cj + 2*Hdim)*4 + cb] + gB[(cj + 2*Hdim)*4 + cb];
            const float vo = gA[(cj + 3*Hdim)*4 + cb] + gB[(cj + 3*Hdim)*4 + cb];
            c1 = fmaf(sigfast(vf), c1, sigfast(vi) * tanhfast(vg));
            ((float*)hcat)[cj*4 + cb] = sigfast(vo) * tanhfast(c1);
        }
        __syncthreads();                                  // #2 h1(t) ready

        // ---- Layer 2 gate partials: fp16 W2 k-quads via LDG.64 ----
        {
            u64 a0 = bb2p, a1 = bb2p;
            const uint2* wp = g_W2H + g;
            #pragma unroll 5
            for (int k4 = k4L2; k4 < k4L2 + 25; ++k4) {
                const uint2 wv = __ldg(wp + k4 * Gdim);                // LDG.64
                const float2 w01 = __half22float2(*reinterpret_cast<const __half2*>(&wv.x));
                const float2 w23 = __half22float2(*reinterpret_cast<const __half2*>(&wv.y));
                const u64 w0 = pack2(w01.x), w1 = pack2(w01.y);
                const u64 w2 = pack2(w23.x), w3 = pack2(w23.y);
                const u64x2 h0 = *(const u64x2*)(hcat + 4*k4);
                const u64x2 h1 = *(const u64x2*)(hcat + 4*k4 + 1);
                const u64x2 h2 = *(const u64x2*)(hcat + 4*k4 + 2);
                const u64x2 h3 = *(const u64x2*)(hcat + 4*k4 + 3);
                fma2(a0, w0, h0.x); fma2(a1, w0, h0.y);
                fma2(a0, w1, h1.x); fma2(a1, w1, h1.y);
                fma2(a0, w2, h2.x); fma2(a1, w2, h2.y);
                fma2(a0, w3, h3.x); fma2(a1, w3, h3.y);
            }
            ulonglong2 r; r.x = a0; r.y = a1;
            if (hA) gatesA[g] = r; else gatesB[g] = r;
        }
        __syncthreads();                                  // #3 gates ready

        // ---- Layer 2 cell update ----
        if (tid < Gdim) {
            const float* gA = (const float*)gatesA;
            const float* gB = (const float*)gatesB;
            const float vi = gA[(cj         )*4 + cb] + gB[(cj         )*4 + cb];
            const float vf = gA[(cj +   Hdim)*4 + cb] + gB[(cj +   Hdim)*4 + cb];
            const float vg = gA[(cj + 2*Hdim)*4 + cb] + gB[(cj + 2*Hdim)*4 + cb];
            const float vo = gA[(cj + 3*Hdim)*4 + cb] + gB[(cj + 3*Hdim)*4 + cb];
            c2 = fmaf(sigfast(vf), c2, sigfast(vi) * tanhfast(vg));
            ((float*)hcat)[(Hdim + cj)*4 + cb] = sigfast(vo) * tanhfast(c2);
        }
        __syncthreads();                                  // #4 h2(t) ready

        // ---- Output projection (warps 0-3); overlaps next L1 in teacher phase ----
        if (tid < 128) {
            const int w = tid >> 5, l = tid & 31;
            float s = 0.f;
            #pragma unroll
            for (int j = 0; j < Hdim; j += 32) {
                const int jj = j + l;
                if (jj < Hdim)
                    s = fmaf(((const float*)hcat)[(Hdim + jj)*4 + w], wlin[jj], s);
            }
            #pragma unroll
            for (int o = 16; o > 0; o >>= 1)
                s += __shfl_down_sync(0xffffffffu, s, o);
            if (l == 0) {
                const float y = s + blin_r;
                out[(b0 + w) * T_TOT + t] = y;
                ((float*)ysv)[w] = y;
            }
        }
        // ysv only feeds x when t+1 >= T_IN; otherwise let warps run ahead.
        if (t >= T_IN - 1) __syncthreads();
    }
}

extern "C" void kernel_launch(void* const* d_in, const int* in_sizes, int n_in,
                              void* d_out, int out_size) {
    const float* input = (const float*)d_in[0];
    const float* W_ih1 = (const float*)d_in[1];
    const float* W_hh1 = (const float*)d_in[2];
    const float* b_ih1 = (const float*)d_in[3];
    const float* b_hh1 = (const float*)d_in[4];
    const float* W_ih2 = (const float*)d_in[5];
    const float* W_hh2 = (const float*)d_in[6];
    const float* b_ih2 = (const float*)d_in[7];
    const float* b_hh2 = (const float*)d_in[8];
    const float* W_lin = (const float*)d_in[9];
    const float* b_lin = (const float*)d_in[10];
    float* out = (float*)d_out;

    prep_weights<<<(50 * Gdim + 255) / 256, 256>>>(W_hh1, W_ih2, W_hh2);

    const int smem_bytes = 48104 * (int)sizeof(float);
    cudaFuncSetAttribute(lstm2_kernel,
                         cudaFuncAttributeMaxDynamicSharedMemorySize, smem_bytes);
    lstm2_kernel<<<NCTA, NTHR, smem_bytes>>>(input, W_ih1, b_ih1, b_hh1,
                                             b_ih2, b_hh2, W_lin, b_lin, out);
}

// round 11
// speedup vs baseline: 1.7297x; 1.0253x over previous
#include <cuda_runtime.h>
#include <cuda_fp16.h>

#define Hdim  100
#define Gdim  400
#define T_IN  1000
#define T_TOT 1300
#define NB    4
#define NCTA  128
#define NTHR  800

// Pre-packed transposed weights (both layers fp16).
__device__ unsigned g_W1H[50 * Gdim];  // W_hh1^T  [k2][g]  fp16 k-pairs
__device__ uint2    g_W2H[50 * Gdim];  // [W_ih2;W_hh2]^T [k4][g]  fp16 k-quads

__global__ void prep_weights(const float* __restrict__ W_hh1,
                             const float* __restrict__ W_ih2,
                             const float* __restrict__ W_hh2) {
    int i = blockIdx.x * blockDim.x + threadIdx.x;
    if (i >= 50 * Gdim) return;
    int kq = i / Gdim, g = i % Gdim;
    {   // W1 fp16 pair: k = 2kq, 2kq+1
        __half2 p = __floats2half2_rn(W_hh1[g*Hdim + 2*kq], W_hh1[g*Hdim + 2*kq + 1]);
        g_W1H[i] = *reinterpret_cast<unsigned*>(&p);
    }
    {   // W2 fp16 quad: k = 4kq .. 4kq+3  (k<100 -> W_ih2, else W_hh2)
        int k = 4 * kq;
        const float* src = (k < Hdim) ? (W_ih2 + g*Hdim + k)
                                      : (W_hh2 + g*Hdim + k - Hdim);
        __half2 p0 = __floats2half2_rn(src[0], src[1]);
        __half2 p1 = __floats2half2_rn(src[2], src[3]);
        uint2 u;
        u.x = *reinterpret_cast<unsigned*>(&p0);
        u.y = *reinterpret_cast<unsigned*>(&p1);
        g_W2H[i] = u;
    }
}

typedef unsigned long long u64;
typedef ulonglong2 u64x2;

__device__ __forceinline__ u64 pack2(float v) {
    u64 r; asm("mov.b64 %0, {%1, %1};" : "=l"(r) : "f"(v)); return r;
}
__device__ __forceinline__ void fma2(u64& a, u64 w, u64 h) {
    asm("fma.rn.f32x2 %0, %1, %2, %0;" : "+l"(a) : "l"(w), "l"(h));
}
__device__ __forceinline__ float tanhfast(float x) {
    float y; asm("tanh.approx.f32 %0, %1;" : "=f"(y) : "f"(x)); return y;
}
__device__ __forceinline__ float sigfast(float x) {
    return fmaf(0.5f, tanhfast(0.5f * x), 0.5f);
}

__global__ __launch_bounds__(NTHR, 1)
void lstm2_kernel(const float* __restrict__ input,
                  const float* __restrict__ W_ih1,
                  const float* __restrict__ b_ih1,
                  const float* __restrict__ b_hh1,
                  const float* __restrict__ b_ih2,
                  const float* __restrict__ b_hh2,
                  const float* __restrict__ W_lin,
                  const float* __restrict__ b_lin,
                  float* __restrict__ out)
{
    extern __shared__ float sm[];
    unsigned*   W1s    = (unsigned*)sm;                  // [50*400] fp16 pairs (20000 f)
    float4*     hcat   = (float4*)(sm + 20000);          // [200] (h1|h2) x 4 batches
    ulonglong2* gatesA = (ulonglong2*)(hcat + 200);      // [400] partial (half A)
    ulonglong2* gatesB = gatesA + Gdim;                  // [400] partial (half B)
    float4*     xin    = (float4*)(gatesB + Gdim);       // [1000] input, t-major
    float4*     ysv    = xin + T_IN;                     // [1]  autoregressive x
    float*      wlin   = (float*)(ysv + 1);              // [100]
    // floats: 20000 + 800 + 1600 + 1600 + 4000 + 4 + 100 = 28104 (112416 B)

    const int tid  = threadIdx.x;
    const int b0   = blockIdx.x * NB;
    const bool hA  = (tid < Gdim);
    const int  g   = hA ? tid : tid - Gdim;

    // ---- one-time init ----
    for (int i = tid; i < 50 * Gdim; i += NTHR) W1s[i] = g_W1H[i];
    for (int i = tid; i < NB * T_IN; i += NTHR) {        // xin[t][b]
        int t = i >> 2, b = i & 3;
        ((float*)xin)[i] = input[(b0 + b) * T_IN + t];
    }
    if (tid < Hdim) wlin[tid] = W_lin[tid];
    for (int i = tid; i < 200 * 4; i += NTHR) ((float*)hcat)[i] = 0.f;
    const float blin_r = __ldg(b_lin);

    // per-thread constants (bias/x-weight only applied by half A)
    const u64 bb1p = hA ? pack2(b_ih1[g] + b_hh1[g]) : 0ull;
    const u64 bb2p = hA ? pack2(b_ih2[g] + b_hh2[g]) : 0ull;
    const u64 wip  = hA ? pack2(W_ih1[g]) : 0ull;
    const int k2L1 = hA ? 0 : 25;    // layer-1 k-pair start (k: 0..49 / 50..99)
    const int k4L2 = hA ? 0 : 25;    // layer-2 k-quad start (k: 0..99 / 100..199)

    const int cj = tid >> 2;         // cell role (tid < 400)
    const int cb = tid & 3;
    float c1 = 0.f, c2 = 0.f;
    __syncthreads();

    for (int t = 0; t < T_TOT; ++t) {
        // ---- Layer 1 gate partials (W1 fp16 from smem, LDS.32 coalesced) ----
        {
            const u64x2 xp = (t < T_IN) ? *(const u64x2*)(xin + t)
                                        : *(const u64x2*)ysv;
            u64 a0 = bb1p, a1 = bb1p;
            if (hA) { fma2(a0, wip, xp.x); fma2(a1, wip, xp.y); }
            const unsigned* wp = W1s + g;
            #pragma unroll 5
            for (int k2 = k2L1; k2 < k2L1 + 25; ++k2) {
                const unsigned wu = wp[k2 * Gdim];                     // 128B/warp
                const float2 w = __half22float2(*reinterpret_cast<const __half2*>(&wu));
                const u64 w0 = pack2(w.x), w1 = pack2(w.y);
                const u64x2 h0 = *(const u64x2*)(hcat + 2*k2);         // broadcast
                const u64x2 h1 = *(const u64x2*)(hcat + 2*k2 + 1);
                fma2(a0, w0, h0.x); fma2(a1, w0, h0.y);
                fma2(a0, w1, h1.x); fma2(a1, w1, h1.y);
            }
            ulonglong2 r; r.x = a0; r.y = a1;
            if (hA) gatesA[g] = r; else gatesB[g] = r;
        }
        __syncthreads();                                  // #1 gates ready

        // ---- Layer 1 cell update (c1 in registers) ----
        if (tid < Gdim) {
            const float* gA = (const float*)gatesA;
            const float* gB = (const float*)gatesB;
            const float vi = gA[(cj         )*4 + cb] + gB[(cj         )*4 + cb];
            const float vf = gA[(cj +   Hdim)*4 + cb] + gB[(cj +   Hdim)*4 + cb];
            const float vg = gA[(cj + 2*Hdim)*4 + cb] + gB[(cj + 2*Hdim)*4 + cb];
            const float vo = gA[(cj + 3*Hdim)*4 + cb] + gB[(cj + 3*Hdim)*4 + cb];
            c1 = fmaf(sigfast(vf), c1, sigfast(vi) * tanhfast(vg));
            ((float*)hcat)[cj*4 + cb] = sigfast(vo) * tanhfast(c1);
        }
        __syncthreads();                                  // #2 h1(t) ready

        // ---- Layer 2 gate partials: fp16 W2 k-quads via LDG.64 ----
        {
            u64 a0 = bb2p, a1 = bb2p;
            const uint2* wp = g_W2H + g;
            #pragma unroll 5
            for (int k4 = k4L2; k4 < k4L2 + 25; ++k4) {
                const uint2 wv = __ldg(wp + k4 * Gdim);                // LDG.64
                const float2 w01 = __half22float2(*reinterpret_cast<const __half2*>(&wv.x));
                const float2 w23 = __half22float2(*reinterpret_cast<const __half2*>(&wv.y));
                const u64 w0 = pack2(w01.x), w1 = pack2(w01.y);
                const u64 w2 = pack2(w23.x), w3 = pack2(w23.y);
                const u64x2 h0 = *(const u64x2*)(hcat + 4*k4);
                const u64x2 h1 = *(const u64x2*)(hcat + 4*k4 + 1);
                const u64x2 h2 = *(const u64x2*)(hcat + 4*k4 + 2);
                const u64x2 h3 = *(const u64x2*)(hcat + 4*k4 + 3);
                fma2(a0, w0, h0.x); fma2(a1, w0, h0.y);
                fma2(a0, w1, h1.x); fma2(a1, w1, h1.y);
                fma2(a0, w2, h2.x); fma2(a1, w2, h2.y);
                fma2(a0, w3, h3.x); fma2(a1, w3, h3.y);
            }
            ulonglong2 r; r.x = a0; r.y = a1;
            if (hA) gatesA[g] = r; else gatesB[g] = r;
        }
        __syncthreads();                                  // #3 gates ready

        // ---- Layer 2 cell update ----
        if (tid < Gdim) {
            const float* gA = (const float*)gatesA;
            const float* gB = (const float*)gatesB;
            const float vi = gA[(cj         )*4 + cb] + gB[(cj         )*4 + cb];
            const float vf = gA[(cj +   Hdim)*4 + cb] + gB[(cj +   Hdim)*4 + cb];
            const float vg = gA[(cj + 2*Hdim)*4 + cb] + gB[(cj + 2*Hdim)*4 + cb];
            const float vo = gA[(cj + 3*Hdim)*4 + cb] + gB[(cj + 3*Hdim)*4 + cb];
            c2 = fmaf(sigfast(vf), c2, sigfast(vi) * tanhfast(vg));
            ((float*)hcat)[(Hdim + cj)*4 + cb] = sigfast(vo) * tanhfast(c2);
        }
        __syncthreads();                                  // #4 h2(t) ready

        // ---- Output projection (warps 0-3); overlaps next L1 in teacher phase ----
        if (tid < 128) {
            const int w = tid >> 5, l = tid & 31;
            float s = 0.f;
            #pragma unroll
            for (int j = 0; j < Hdim; j += 32) {
                const int jj = j + l;
                if (jj < Hdim)
                    s = fmaf(((const float*)hcat)[(Hdim + jj)*4 + w], wlin[jj], s);
            }
            #pragma unroll
            for (int o = 16; o > 0; o >>= 1)
                s += __shfl_down_sync(0xffffffffu, s, o);
            if (l == 0) {
                const float y = s + blin_r;
                out[(b0 + w) * T_TOT + t] = y;
                ((float*)ysv)[w] = y;
            }
        }
        // ysv only feeds x when t+1 >= T_IN; otherwise let warps run ahead.
        if (t >= T_IN - 1) __syncthreads();
    }
}

extern "C" void kernel_launch(void* const* d_in, const int* in_sizes, int n_in,
                              void* d_out, int out_size) {
    const float* input = (const float*)d_in[0];
    const float* W_ih1 = (const float*)d_in[1];
    const float* W_hh1 = (const float*)d_in[2];
    const float* b_ih1 = (const float*)d_in[3];
    const float* b_hh1 = (const float*)d_in[4];
    const float* W_ih2 = (const float*)d_in[5];
    const float* W_hh2 = (const float*)d_in[6];
    const float* b_ih2 = (const float*)d_in[7];
    const float* b_hh2 = (const float*)d_in[8];
    const float* W_lin = (const float*)d_in[9];
    const float* b_lin = (const float*)d_in[10];
    float* out = (float*)d_out;

    prep_weights<<<(50 * Gdim + 255) / 256, 256>>>(W_hh1, W_ih2, W_hh2);

    const int smem_bytes = 28104 * (int)sizeof(float);
    cudaFuncSetAttribute(lstm2_kernel,
                         cudaFuncAttributeMaxDynamicSharedMemorySize, smem_bytes);
    lstm2_kernel<<<NCTA, NTHR, smem_bytes>>>(input, W_ih1, b_ih1, b_hh1,
                                             b_ih2, b_hh2, W_lin, b_lin, out);
}

// round 12
// speedup vs baseline: 2.0794x; 1.2021x over previous
#include <cuda_runtime.h>
#include <cuda_fp16.h>

#define Hdim  100
#define Gdim  400
#define T_IN  1000
#define T_TOT 1300
#define NB    4
#define NCTA  128
#define NTHR  800

// Gate-pair packed fp16 weights: [k2][p] -> uint2{ half2(gate p, k=2k2,2k2+1),
//                                                  half2(gate p+200, same k) }
__device__ uint2 g_W1P2[52 * 200];    // W_hh1, zero-padded k2 in {50,51}
__device__ uint2 g_W2P2[100 * 200];   // [W_ih2; W_hh2] over k<200

__global__ void prep_weights(const float* __restrict__ W_hh1,
                             const float* __restrict__ W_ih2,
                             const float* __restrict__ W_hh2) {
    int i = blockIdx.x * blockDim.x + threadIdx.x;
    if (i < 52 * 200) {
        int k2 = i / 200, p = i % 200, k = 2 * k2;
        uint2 u;
        if (k2 < 50) {
            __half2 a = __floats2half2_rn(W_hh1[p*Hdim + k],       W_hh1[p*Hdim + k + 1]);
            __half2 b = __floats2half2_rn(W_hh1[(p+200)*Hdim + k], W_hh1[(p+200)*Hdim + k + 1]);
            u.x = *reinterpret_cast<unsigned*>(&a);
            u.y = *reinterpret_cast<unsigned*>(&b);
        } else { u.x = 0u; u.y = 0u; }
        g_W1P2[i] = u;
    }
    if (i < 100 * 200) {
        int k2 = i / 200, p = i % 200, k = 2 * k2;
        const float* s0 = (k < Hdim) ? (W_ih2 + p*Hdim + k)       : (W_hh2 + p*Hdim + k - Hdim);
        const float* s1 = (k < Hdim) ? (W_ih2 + (p+200)*Hdim + k) : (W_hh2 + (p+200)*Hdim + k - Hdim);
        __half2 a = __floats2half2_rn(s0[0], s0[1]);
        __half2 b = __floats2half2_rn(s1[0], s1[1]);
        uint2 u;
        u.x = *reinterpret_cast<unsigned*>(&a);
        u.y = *reinterpret_cast<unsigned*>(&b);
        g_W2P2[i] = u;
    }
}

typedef unsigned long long u64;
typedef ulonglong2 u64x2;

__device__ __forceinline__ u64 pack2(float v) {
    u64 r; asm("mov.b64 %0, {%1, %1};" : "=l"(r) : "f"(v)); return r;
}
__device__ __forceinline__ void fma2(u64& a, u64 w, u64 h) {
    asm("fma.rn.f32x2 %0, %1, %2, %0;" : "+l"(a) : "l"(w), "l"(h));
}
__device__ __forceinline__ float tanhfast(float x) {
    float y; asm("tanh.approx.f32 %0, %1;" : "=f"(y) : "f"(x)); return y;
}
__device__ __forceinline__ float sigfast(float x) {
    return fmaf(0.5f, tanhfast(0.5f * x), 0.5f);
}

__global__ __launch_bounds__(NTHR, 1)
void lstm2_kernel(const float* __restrict__ input,
                  const float* __restrict__ W_ih1,
                  const float* __restrict__ b_ih1,
                  const float* __restrict__ b_hh1,
                  const float* __restrict__ b_ih2,
                  const float* __restrict__ b_hh2,
                  const float* __restrict__ W_lin,
                  const float* __restrict__ b_lin,
                  float* __restrict__ out)
{
    extern __shared__ float sm[];
    uint2*  W1s  = (uint2*)sm;                    // [52*200]  (20800 floats)
    float4* hcat = (float4*)(sm + 20800);         // [200] (h1|h2) x 4 batches
    u64x2*  gq   = (u64x2*)(sm + 21600);          // [4][400] quarter partials (6400 f)
    float4* xin  = (float4*)(sm + 28000);         // [1000] input t-major
    float4* ysv  = (float4*)(sm + 32000);         // [1]
    float*  wlin = sm + 32004;                    // [100]
    // total 32104 floats = 128416 B

    const int tid = threadIdx.x;
    const int b0  = blockIdx.x * NB;
    const int kq  = tid / 200;       // k-quarter 0..3
    const int p   = tid % 200;       // gate-pair: gates p and p+200

    // ---- one-time init ----
    for (int i = tid; i < 52 * 200 * 2; i += NTHR)
        ((unsigned*)W1s)[i] = ((const unsigned*)g_W1P2)[i];
    for (int i = tid; i < NB * T_IN; i += NTHR) {
        int t = i >> 2, b = i & 3;
        ((float*)xin)[i] = input[(b0 + b) * T_IN + t];
    }
    if (tid < Hdim) wlin[tid] = W_lin[tid];
    for (int i = tid; i < 200 * 4; i += NTHR) ((float*)hcat)[i] = 0.f;
    const float blin_r = __ldg(b_lin);

    // bias/x-weight constants, applied by quarter 0 only
    u64 bb1_0 = 0, bb1_1 = 0, wi_0 = 0, wi_1 = 0, bb2_0 = 0, bb2_1 = 0;
    if (kq == 0) {
        bb1_0 = pack2(b_ih1[p]       + b_hh1[p]);
        bb1_1 = pack2(b_ih1[p + 200] + b_hh1[p + 200]);
        wi_0  = pack2(W_ih1[p]);
        wi_1  = pack2(W_ih1[p + 200]);
        bb2_0 = pack2(b_ih2[p]       + b_hh2[p]);
        bb2_1 = pack2(b_ih2[p + 200] + b_hh2[p + 200]);
    }
    const int k2L1 = kq * 13;        // L1 k-pair range [k2L1, k2L1+13), padded to 52
    const int k2L2 = kq * 25;        // L2 k-pair range [k2L2, k2L2+25)

    const int cj = tid >> 2;         // cell role (tid < 400)
    const int cb = tid & 3;
    float c1 = 0.f, c2 = 0.f;
    __syncthreads();

    for (int t = 0; t < T_TOT; ++t) {
        // ---- Layer 1 gate partials: 2 gates/thread, fp16 W1 from smem ----
        {
            const u64x2 xp = (t < T_IN) ? *(const u64x2*)(xin + t)
                                        : *(const u64x2*)ysv;
            u64 a00 = bb1_0, a01 = bb1_0, a10 = bb1_1, a11 = bb1_1;
            if (kq == 0) {
                fma2(a00, wi_0, xp.x); fma2(a01, wi_0, xp.y);
                fma2(a10, wi_1, xp.x); fma2(a11, wi_1, xp.y);
            }
            const uint2* wp = W1s + p;
            #pragma unroll 13
            for (int k2 = k2L1; k2 < k2L1 + 13; ++k2) {
                const uint2 wu = wp[k2 * 200];                   // LDS.64
                const float2 wA = __half22float2(*reinterpret_cast<const __half2*>(&wu.x));
                const float2 wB = __half22float2(*reinterpret_cast<const __half2*>(&wu.y));
                const u64x2 h0 = *(const u64x2*)(hcat + 2*k2);   // broadcast
                const u64x2 h1 = *(const u64x2*)(hcat + 2*k2 + 1);
                const u64 wA0 = pack2(wA.x), wA1 = pack2(wA.y);
                const u64 wB0 = pack2(wB.x), wB1 = pack2(wB.y);
                fma2(a00, wA0, h0.x); fma2(a01, wA0, h0.y);
                fma2(a00, wA1, h1.x); fma2(a01, wA1, h1.y);
                fma2(a10, wB0, h0.x); fma2(a11, wB0, h0.y);
                fma2(a10, wB1, h1.x); fma2(a11, wB1, h1.y);
            }
            u64x2 r0; r0.x = a00; r0.y = a01;
            u64x2 r1; r1.x = a10; r1.y = a11;
            gq[kq * 400 + p]       = r0;
            gq[kq * 400 + p + 200] = r1;
        }
        __syncthreads();                                  // #1 gates ready

        // ---- Layer 1 cell update (sum 4 quarter partials) ----
        if (tid < Gdim) {
            const float* G = (const float*)gq;
            float vi = 0.f, vf = 0.f, vg = 0.f, vo = 0.f;
            #pragma unroll
            for (int q = 0; q < 4; ++q) {
                vi += G[(q*400 +       cj)*4 + cb];
                vf += G[(q*400 + 100 + cj)*4 + cb];
                vg += G[(q*400 + 200 + cj)*4 + cb];
                vo += G[(q*400 + 300 + cj)*4 + cb];
            }
            c1 = fmaf(sigfast(vf), c1, sigfast(vi) * tanhfast(vg));
            ((float*)hcat)[cj*4 + cb] = sigfast(vo) * tanhfast(c1);
        }
        __syncthreads();                                  // #2 h1(t) ready

        // ---- Layer 2 gate partials: 2 gates/thread, fp16 W2 via LDG.64 ----
        {
            u64 a00 = bb2_0, a01 = bb2_0, a10 = bb2_1, a11 = bb2_1;
            const uint2* wp = g_W2P2 + p;
            #pragma unroll 5
            for (int k2 = k2L2; k2 < k2L2 + 25; ++k2) {
                const uint2 wu = __ldg(wp + k2 * 200);           // LDG.64
                const float2 wA = __half22float2(*reinterpret_cast<const __half2*>(&wu.x));
                const float2 wB = __half22float2(*reinterpret_cast<const __half2*>(&wu.y));
                const u64x2 h0 = *(const u64x2*)(hcat + 2*k2);
                const u64x2 h1 = *(const u64x2*)(hcat + 2*k2 + 1);
                const u64 wA0 = pack2(wA.x), wA1 = pack2(wA.y);
                const u64 wB0 = pack2(wB.x), wB1 = pack2(wB.y);
                fma2(a00, wA0, h0.x); fma2(a01, wA0, h0.y);
                fma2(a00, wA1, h1.x); fma2(a01, wA1, h1.y);
                fma2(a10, wB0, h0.x); fma2(a11, wB0, h0.y);
                fma2(a10, wB1, h1.x); fma2(a11, wB1, h1.y);
            }
            u64x2 r0; r0.x = a00; r0.y = a01;
            u64x2 r1; r1.x = a10; r1.y = a11;
            gq[kq * 400 + p]       = r0;
            gq[kq * 400 + p + 200] = r1;
        }
        __syncthreads();                                  // #3 gates ready

        // ---- Layer 2 cell update ----
        if (tid < Gdim) {
            const float* G = (const float*)gq;
            float vi = 0.f, vf = 0.f, vg = 0.f, vo = 0.f;
            #pragma unroll
            for (int q = 0; q < 4; ++q) {
                vi += G[(q*400 +       cj)*4 + cb];
                vf += G[(q*400 + 100 + cj)*4 + cb];
                vg += G[(q*400 + 200 + cj)*4 + cb];
                vo += G[(q*400 + 300 + cj)*4 + cb];
            }
            c2 = fmaf(sigfast(vf), c2, sigfast(vi) * tanhfast(vg));
            ((float*)hcat)[(Hdim + cj)*4 + cb] = sigfast(vo) * tanhfast(c2);
        }
        __syncthreads();                                  // #4 h2(t) ready

        // ---- Output projection (warps 0-3); overlaps next L1 in teacher phase ----
        if (tid < 128) {
            const int w = tid >> 5, l = tid & 31;
            float s = 0.f;
            #pragma unroll
            for (int j = 0; j < Hdim; j += 32) {
                const int jj = j + l;
                if (jj < Hdim)
                    s = fmaf(((const float*)hcat)[(Hdim + jj)*4 + w], wlin[jj], s);
            }
            #pragma unroll
            for (int o = 16; o > 0; o >>= 1)
                s += __shfl_down_sync(0xffffffffu, s, o);
            if (l == 0) {
                const float y = s + blin_r;
                out[(b0 + w) * T_TOT + t] = y;
                ((float*)ysv)[w] = y;
            }
        }
        // ysv only feeds x when t+1 >= T_IN; otherwise let warps run ahead.
        if (t >= T_IN - 1) __syncthreads();
    }
}

extern "C" void kernel_launch(void* const* d_in, const int* in_sizes, int n_in,
                              void* d_out, int out_size) {
    const float* input = (const float*)d_in[0];
    const float* W_ih1 = (const float*)d_in[1];
    const float* W_hh1 = (const float*)d_in[2];
    const float* b_ih1 = (const float*)d_in[3];
    const float* b_hh1 = (const float*)d_in[4];
    const float* W_ih2 = (const float*)d_in[5];
    const float* W_hh2 = (const float*)d_in[6];
    const float* b_ih2 = (const float*)d_in[7];
    const float* b_hh2 = (const float*)d_in[8];
    const float* W_lin = (const float*)d_in[9];
    const float* b_lin = (const float*)d_in[10];
    float* out = (float*)d_out;

    prep_weights<<<(100 * 200 + 255) / 256, 256>>>(W_hh1, W_ih2, W_hh2);

    const int smem_bytes = 32104 * (int)sizeof(float);
    cudaFuncSetAttribute(lstm2_kernel,
                         cudaFuncAttributeMaxDynamicSharedMemorySize, smem_bytes);
    lstm2_kernel<<<NCTA, NTHR, smem_bytes>>>(input, W_ih1, b_ih1, b_hh1,
                                             b_ih2, b_hh2, W_lin, b_lin, out);
}